// round 12
// baseline (speedup 1.0000x reference)
#include <cuda_runtime.h>
#include <cuda_fp16.h>
#include <math.h>
#include <stdint.h>

// ---------------- problem constants ----------------
#define NV    5023
#define C3    15069
#define C3PAD 15072
#define NW5   25120
#define NJ    5
#define KTOT  192
#define NMAX  2048

// ---------------- device scratch ----------------
__device__ float g_JS[NJ * 3 * 150];
__device__ float g_JT[NJ * 3];
__device__ __align__(16) __half g_pvec[NMAX * KTOT];
// g_Amat: batch-PAIR interleaved: [pair][element 0..59][2 batches]
__device__ __align__(16) float g_Amat[NMAX * NJ * 12];
__device__ __align__(16) __half g_B[C3PAD * KTOT];
__device__ __align__(16) float g_Wp[NW5];
__device__ __align__(16) float g_VTp[C3PAD];

// ---------------- helpers ----------------
__device__ __forceinline__ uint32_t smem_u32(const void* p) {
    uint32_t a;
    asm("{ .reg .u64 t; cvta.to.shared.u64 t, %1; cvt.u32.u64 %0, t; }" : "=r"(a) : "l"(p));
    return a;
}
__device__ __forceinline__ void mma_f16_16x8x16(float* d, const uint32_t* a,
                                                uint32_t b0, uint32_t b1) {
    asm volatile(
        "mma.sync.aligned.m16n8k16.row.col.f32.f16.f16.f32 "
        "{%0,%1,%2,%3}, {%4,%5,%6,%7}, {%8,%9}, {%0,%1,%2,%3};"
        : "+f"(d[0]), "+f"(d[1]), "+f"(d[2]), "+f"(d[3])
        : "r"(a[0]), "r"(a[1]), "r"(a[2]), "r"(a[3]), "r"(b0), "r"(b1));
}
#define LDSM_X4(r, addr)                                                     \
    asm volatile("ldmatrix.sync.aligned.m8n8.x4.shared.b16 {%0,%1,%2,%3}, [%4];" \
        : "=r"((r)[0]), "=r"((r)[1]), "=r"((r)[2]), "=r"((r)[3]) : "r"(addr))
__device__ __forceinline__ unsigned long long fma2(unsigned long long a,
                                                   unsigned long long b,
                                                   unsigned long long c) {
    unsigned long long d;
    asm("fma.rn.f32x2 %0, %1, %2, %3;" : "=l"(d) : "l"(a), "l"(b), "l"(c));
    return d;
}
__device__ __forceinline__ unsigned long long add2(unsigned long long a, unsigned long long b) {
    unsigned long long d;
    asm("add.rn.f32x2 %0, %1, %2;" : "=l"(d) : "l"(a), "l"(b));
    return d;
}
__device__ __forceinline__ unsigned long long packb(float x) {
    unsigned long long d;
    asm("mov.b64 %0, {%1, %1};" : "=l"(d) : "f"(x));
    return d;
}
__device__ __forceinline__ unsigned long long packp(float lo, float hi) {
    unsigned long long d;
    asm("mov.b64 %0, {%1, %2};" : "=l"(d) : "f"(lo), "f"(hi));
    return d;
}
__device__ __forceinline__ void unpk(unsigned long long v, float& lo, float& hi) {
    asm("mov.b64 {%0, %1}, %2;" : "=f"(lo), "=f"(hi) : "l"(v));
}
#define CP_ASYNC16(dst, src) \
    asm volatile("cp.async.cg.shared.global [%0], [%1], 16;" :: "r"(dst), "l"(src))
#define CP_COMMIT()  asm volatile("cp.async.commit_group;" ::: "memory")
#define CP_WAIT(n)   asm volatile("cp.async.wait_group %0;" :: "n"(n) : "memory")

// ---------------- kernel 0a ----------------
__global__ void k_zero() {
    int t = blockIdx.x * blockDim.x + threadIdx.x;
    if (t < NJ * 3 * 150) g_JS[t] = 0.0f;
    if (t < NJ * 3)       g_JT[t] = 0.0f;
}

// ---------------- kernel 0b: JS/JT reduction (157 blocks) + fused B build + pads ----------------
#define JSB 157
__global__ void k_prep(const float* __restrict__ Jr, const float* __restrict__ SD,
                       const float* __restrict__ PD, const float* __restrict__ VT,
                       const float* __restrict__ W) {
    if (blockIdx.x < JSB) {
        __shared__ float sJr[NJ][32];
        int vb = blockIdx.x * 32;
        int ve = vb + 32; if (ve > NV) ve = NV;
        int nv = ve - vb;
        int t = threadIdx.x;
        if (t < NJ * 32) {
            int j = t >> 5, v = t & 31;
            sJr[j][v] = (vb + v < NV) ? Jr[j * NV + vb + v] : 0.0f;
        }
        __syncthreads();
        if (t < 450) {
            float acc[NJ] = {0.f, 0.f, 0.f, 0.f, 0.f};
            for (int v = 0; v < nv; ++v) {
                float sd = SD[(vb + v) * 450 + t];
#pragma unroll
                for (int j = 0; j < NJ; j++) acc[j] = fmaf(sJr[j][v], sd, acc[j]);
            }
#pragma unroll
            for (int j = 0; j < NJ; j++) atomicAdd(&g_JS[j * 450 + t], acc[j]);
        } else if (t < 453) {
            int kc = t - 450;
            float acc[NJ] = {0.f, 0.f, 0.f, 0.f, 0.f};
            for (int v = 0; v < nv; ++v) {
                float vt = VT[(vb + v) * 3 + kc];
#pragma unroll
                for (int j = 0; j < NJ; j++) acc[j] = fmaf(sJr[j][v], vt, acc[j]);
            }
#pragma unroll
            for (int j = 0; j < NJ; j++) atomicAdd(&g_JT[j * 3 + kc], acc[j]);
        }
    } else {
        int idx = (blockIdx.x - JSB) * 512 + threadIdx.x;
        if (idx < NW5)   g_Wp[idx]  = (idx < NV * 5) ? W[idx]  : 0.0f;
        if (idx < C3PAD) g_VTp[idx] = (idx < C3)     ? VT[idx] : 0.0f;
        if (idx >= C3PAD * KTOT) return;
        int col = idx / KTOT;
        int k = idx - col * KTOT;
        float val = 0.0f;
        if (col < C3) {
            int v = col / 3, kc = col - v * 3;
            if (k < 150)      val = SD[v * 450 + kc * 150 + k];
            else if (k < 186) val = PD[(k - 150) * C3 + col];
        }
        g_B[idx] = __float2half_rn(val);
    }
}

// ---------------- rodrigues / chain ----------------
__device__ __forceinline__ void rodr(float x, float y, float z, float* R) {
    float a0 = x + 1e-8f, a1 = y + 1e-8f, a2 = z + 1e-8f;
    float ang = sqrtf(a0 * a0 + a1 * a1 + a2 * a2);
    float inv = 1.0f / ang;
    float rx = x * inv, ry = y * inv, rz = z * inv;
    float s = sinf(ang), c = cosf(ang), t = 1.0f - c;
    R[0] = 1.0f - t * (ry * ry + rz * rz);
    R[1] = t * rx * ry - s * rz;
    R[2] = t * rx * rz + s * ry;
    R[3] = t * rx * ry + s * rz;
    R[4] = 1.0f - t * (rx * rx + rz * rz);
    R[5] = t * ry * rz - s * rx;
    R[6] = t * rx * rz - s * ry;
    R[7] = t * ry * rz + s * rx;
    R[8] = 1.0f - t * (rx * rx + ry * ry);
}
__device__ __forceinline__ void mm3(const float* A, const float* B, float* C) {
#pragma unroll
    for (int r = 0; r < 3; r++)
#pragma unroll
        for (int c = 0; c < 3; c++)
            C[r * 3 + c] = A[r * 3 + 0] * B[0 + c] + A[r * 3 + 1] * B[3 + c] + A[r * 3 + 2] * B[6 + c];
}

// ---------------- kernel 1: per-batch params ----------------
__global__ __launch_bounds__(256) void k_batch(const float* __restrict__ shp, const float* __restrict__ ex,
                        const float* __restrict__ neck, const float* __restrict__ jaw,
                        const float* __restrict__ eye, int N) {
    __shared__ float sJS[2250];
    __shared__ float sJT[15];
    int tid = threadIdx.x;
    for (int i = tid; i < 2250; i += 256) sJS[i] = g_JS[i];
    if (tid < 15) sJT[tid] = g_JT[tid];
    __syncthreads();

    int b = (blockIdx.x * blockDim.x + tid) >> 5;
    int lane = tid & 31;
    if (b >= N) return;

    float Jp[15];
#pragma unroll
    for (int i = 0; i < 15; i++) Jp[i] = 0.0f;

    for (int l = lane; l < 150; l += 32) {
        float beta = (l < 100) ? shp[b * 100 + l] : ex[b * 50 + (l - 100)];
        g_pvec[b * KTOT + l] = __float2half_rn(beta);
#pragma unroll
        for (int jk = 0; jk < 15; jk++)
            Jp[jk] = fmaf(sJS[jk * 150 + l], beta, Jp[jk]);
    }
    for (int i = 150 + lane; i < KTOT; i += 32) g_pvec[b * KTOT + i] = __float2half_rn(0.0f);

#pragma unroll
    for (int jk = 0; jk < 15; jk++) {
#pragma unroll
        for (int off = 16; off; off >>= 1)
            Jp[jk] += __shfl_down_sync(0xffffffffu, Jp[jk], off);
    }
    __syncwarp();

    if (lane == 0) {
        float J[5][3];
#pragma unroll
        for (int j = 0; j < 5; j++)
#pragma unroll
            for (int kc = 0; kc < 3; kc++)
                J[j][kc] = Jp[j * 3 + kc] + sJT[j * 3 + kc];

        float R[5][9];
#pragma unroll
        for (int e = 0; e < 9; e++) R[0][e] = (e == 0 || e == 4 || e == 8) ? 1.0f : 0.0f;
        rodr(neck[b * 3 + 0], neck[b * 3 + 1], neck[b * 3 + 2], R[1]);
        rodr(jaw[b * 3 + 0],  jaw[b * 3 + 1],  jaw[b * 3 + 2],  R[2]);
        rodr(eye[b * 6 + 0],  eye[b * 6 + 1],  eye[b * 6 + 2],  R[3]);
        rodr(eye[b * 6 + 3],  eye[b * 6 + 4],  eye[b * 6 + 5],  R[4]);

        __half* pf = &g_pvec[b * KTOT + 150];
#pragma unroll
        for (int j = 1; j < 5; j++)
#pragma unroll
            for (int e = 0; e < 9; e++)
                pf[(j - 1) * 9 + e] = __float2half_rn(R[j][e] - ((e == 0 || e == 4 || e == 8) ? 1.0f : 0.0f));

        float Rg[5][9], tg[5][3];
#pragma unroll
        for (int e = 0; e < 9; e++) Rg[0][e] = R[0][e];
#pragma unroll
        for (int kc = 0; kc < 3; kc++) tg[0][kc] = J[0][kc];
#pragma unroll
        for (int i = 1; i < 5; i++) {
            const int p = (i == 1) ? 0 : 1;
            mm3(Rg[p], R[i], Rg[i]);
            float r0 = J[i][0] - J[p][0], r1 = J[i][1] - J[p][1], r2 = J[i][2] - J[p][2];
#pragma unroll
            for (int r = 0; r < 3; r++)
                tg[i][r] = Rg[p][r * 3 + 0] * r0 + Rg[p][r * 3 + 1] * r1 + Rg[p][r * 3 + 2] * r2 + tg[p][r];
        }
        float* Am = &g_Amat[(b >> 1) * 120 + (b & 1)];
#pragma unroll
        for (int j = 0; j < 5; j++)
#pragma unroll
            for (int r = 0; r < 3; r++) {
                Am[(j * 12 + r * 4 + 0) * 2] = Rg[j][r * 3 + 0];
                Am[(j * 12 + r * 4 + 1) * 2] = Rg[j][r * 3 + 1];
                Am[(j * 12 + r * 4 + 2) * 2] = Rg[j][r * 3 + 2];
                Am[(j * 12 + r * 4 + 3) * 2] = tg[j][r]
                    - (Rg[j][r * 3 + 0] * J[j][0] + Rg[j][r * 3 + 1] * J[j][1] + Rg[j][r * 3 + 2] * J[j][2]);
            }
    }
}

// ---------------- kernel 2: monolithic-K fp16 mma GEMM + FFMA2 LBS ----------------
// smem bytes: A@0 (128 rows x 400 B = 51200) | B@51200 (96 x 400 = 38400) | end 89600
//             EW@89600 (640) | EVT@90240 (384) | DYN 90624
// res (f32 128x100 = 51200 B) reuses the A region after MMAs complete.
// A-matrices are read from L2 during the LBS (8-thread broadcast per address).
#define STRB 400      // bytes per smem row (192 halfs + 8 pad)
#define OFF_A 0
#define OFF_B 51200
#define OFF_EW  89600
#define OFF_EVT 90240
#define DYN_BYTES 90624

__global__ __launch_bounds__(256) void k_main(float* __restrict__ out, int N) {
    extern __shared__ float SM[];
    const uint32_t sbase = smem_u32(SM);

    const int tid = threadIdx.x;
    const int wid = tid >> 5, lane = tid & 31;
    const int q = lane & 3, g = lane >> 2;
    const int wm = wid & 3, wn = wid >> 2;
    const int v0 = blockIdx.x * 32;
    const int b0 = blockIdx.y * 128;

    // load half kh (k in [kh*96, kh*96+96)) of A and B tiles
    auto load_half = [&](int kh) {
#pragma unroll
        for (int i = 0; i < 6; i++) {            // A: 128 rows x 12 segs = 1536
            int idx = i * 256 + tid;
            int r = idx / 12, s = idx - r * 12;
            int b = b0 + r; if (b >= N) b = N - 1;
            const __half* src = &g_pvec[b * KTOT + kh * 96 + s * 8];
            CP_ASYNC16(sbase + OFF_A + r * STRB + (kh * 12 + s) * 16, src);
        }
#pragma unroll
        for (int i = 0; i < 5; i++) {            // B: 96 rows x 12 segs = 1152
            int idx = i * 256 + tid;
            if (idx < 1152) {
                int r = idx / 12, s = idx - r * 12;
                const __half* src = &g_B[(v0 * 3 + r) * KTOT + kh * 96 + s * 8];
                CP_ASYNC16(sbase + OFF_B + r * STRB + (kh * 12 + s) * 16, src);
            }
        }
    };

    // W/VT prefetch joins first group
    if (tid < 40) CP_ASYNC16(sbase + OFF_EW + tid * 16, &g_Wp[v0 * 5 + tid * 4]);
    if (tid < 24) CP_ASYNC16(sbase + OFF_EVT + tid * 16, &g_VTp[v0 * 3 + tid * 4]);
    load_half(0);
    CP_COMMIT();
    load_half(1);
    CP_COMMIT();

    // ldmatrix lane base addresses
    const uint32_t rowA = wm * 32 + ((lane >> 3) & 1) * 8 + (lane & 7);
    const uint32_t koffA = (lane >> 4) * 8;
    const uint32_t aBase = sbase + OFF_A + rowA * STRB + koffA * 2;
    const uint32_t rowB = wn * 48 + ((lane >> 4) & 1) * 8 + (lane & 7);
    const uint32_t koffB = ((lane >> 3) & 1) * 8;
    const uint32_t bBase = sbase + OFF_B + rowB * STRB + koffB * 2;

    float acc[2][6][4];
#pragma unroll
    for (int mi = 0; mi < 2; mi++)
#pragma unroll
        for (int ni = 0; ni < 6; ni++)
#pragma unroll
            for (int r = 0; r < 4; r++) acc[mi][ni][r] = 0.0f;

    CP_WAIT(1);
    __syncthreads();

#pragma unroll
    for (int s = 0; s < 12; s++) {
        if (s == 6) {
            CP_WAIT(0);
            __syncthreads();
        }
        uint32_t a[2][4], bfr[3][4];
        LDSM_X4(a[0], aBase + s * 32);
        LDSM_X4(a[1], aBase + 16 * STRB + s * 32);
#pragma unroll
        for (int t = 0; t < 3; t++)
            LDSM_X4(bfr[t], bBase + t * 16 * STRB + s * 32);
#pragma unroll
        for (int mi = 0; mi < 2; mi++)
#pragma unroll
            for (int ni = 0; ni < 6; ni++)
                mma_f16_16x8x16(acc[mi][ni], a[mi],
                                bfr[ni >> 1][(ni & 1) * 2],
                                bfr[ni >> 1][(ni & 1) * 2 + 1]);
    }
    __syncthreads();   // all MMAs done -> A region reusable as res

    // ---------------- stage GEMM result ----------------
    float* res = SM;                         // 128x100 f32 (A region)
    const float* sW  = (const float*)((char*)SM + OFF_EW);
    const float* sVt = (const float*)((char*)SM + OFF_EVT);
#pragma unroll
    for (int mi = 0; mi < 2; mi++)
#pragma unroll
        for (int ni = 0; ni < 6; ni++)
#pragma unroll
            for (int r = 0; r < 4; r++) {
                int row = wm * 32 + mi * 16 + g + (r >> 1) * 8;
                int col = wn * 48 + ni * 8 + q * 2 + (r & 1);
                res[row * 100 + col] = acc[mi][ni][r];
            }
    __syncthreads();

    // ---------------- FFMA2 LBS, packed across batch pairs (A-matrices from L2) ----------------
    const int vg = tid & 7;     // 4 vertices per thread
    const int bg = tid >> 3;    // 4 batches = 2 pairs per thread

    unsigned long long wb[4][5], vtb[4][3];
#pragma unroll
    for (int vi = 0; vi < 4; vi++) {
        int vl = vg * 4 + vi;
#pragma unroll
        for (int j = 0; j < 5; j++) wb[vi][j] = packb(sW[vl * 5 + j]);
#pragma unroll
        for (int m = 0; m < 3; m++) vtb[vi][m] = packb(sVt[vl * 3 + m]);
    }

#pragma unroll
    for (int u = 0; u < 2; u++) {
        const int pl = bg * 2 + u;
        const unsigned long long* Ap =
            (const unsigned long long*)&g_Amat[((b0 >> 1) + pl) * 120];
        float* r0p = &res[(2 * pl) * 100];
        float* r1p = &res[(2 * pl + 1) * 100];

        unsigned long long vp2[4][3];
#pragma unroll
        for (int vi = 0; vi < 4; vi++) {
            int c = (vg * 4 + vi) * 3;
#pragma unroll
            for (int m = 0; m < 3; m++)
                vp2[vi][m] = add2(packp(r0p[c + m], r1p[c + m]), vtb[vi][m]);
        }

#pragma unroll
        for (int r = 0; r < 3; r++) {
            unsigned long long A2[5][4];
#pragma unroll
            for (int j = 0; j < 5; j++)
#pragma unroll
                for (int m = 0; m < 4; m++)
                    A2[j][m] = Ap[j * 12 + r * 4 + m];
#pragma unroll
            for (int vi = 0; vi < 4; vi++) {
                unsigned long long s2 = 0ULL;
#pragma unroll
                for (int j = 0; j < 5; j++) {
                    unsigned long long t2 =
                        fma2(A2[j][0], vp2[vi][0],
                        fma2(A2[j][1], vp2[vi][1],
                        fma2(A2[j][2], vp2[vi][2], A2[j][3])));
                    s2 = fma2(wb[vi][j], t2, s2);
                }
                float lo, hi;
                unpk(s2, lo, hi);
                int c = (vg * 4 + vi) * 3 + r;
                r0p[c] = lo;
                r1p[c] = hi;
            }
        }
    }
    __syncthreads();

    // ---------------- coalesced store ----------------
    const int cmax = C3 - v0 * 3;
#pragma unroll
    for (int i = 0; i < 48; i++) {
        int idx = i * 256 + tid;
        int bl = idx / 96, c = idx - bl * 96;
        int b = b0 + bl;
        if (b < N && c < cmax)
            out[(size_t)b * C3 + v0 * 3 + c] = res[bl * 100 + c];
    }
}

// ---------------- launch ----------------
extern "C" void kernel_launch(void* const* d_in, const int* in_sizes, int n_in,
                              void* d_out, int out_size) {
    const float* shp  = (const float*)d_in[0];
    const float* ex   = (const float*)d_in[1];
    const float* neck = (const float*)d_in[2];
    const float* jaw  = (const float*)d_in[3];
    const float* eye  = (const float*)d_in[4];
    const float* vt   = (const float*)d_in[5];
    const float* sd   = (const float*)d_in[6];
    const float* pd   = (const float*)d_in[7];
    const float* jr   = (const float*)d_in[8];
    const float* lw   = (const float*)d_in[9];
    int N = in_sizes[0] / 100;
    if (N > NMAX) N = NMAX;

    static int smem_set = 0;
    if (!smem_set) {
        cudaFuncSetAttribute(k_main, cudaFuncAttributeMaxDynamicSharedMemorySize, DYN_BYTES);
        smem_set = 1;
    }

    k_zero<<<9, 256>>>();
    k_prep<<<JSB + (C3PAD * KTOT + 511) / 512, 512>>>(jr, sd, pd, vt, lw);
    k_batch<<<(N + 7) / 8, 256>>>(shp, ex, neck, jaw, eye, N);

    dim3 grid((NV + 31) / 32, (N + 127) / 128);
    k_main<<<grid, 256, DYN_BYTES>>>((float*)d_out, N);
}

// round 13
// speedup vs baseline: 1.2769x; 1.2769x over previous
#include <cuda_runtime.h>
#include <cuda_fp16.h>
#include <math.h>
#include <stdint.h>

// ---------------- problem constants ----------------
#define NV    5023
#define C3    15069
#define C3PAD 15072
#define NW5   25120
#define NJ    5
#define KTOT  192
#define NMAX  2048
#define KC    64
#define NCH   3

// ---------------- device scratch ----------------
__device__ float g_JS[NJ * 3 * 150];
__device__ float g_JT[NJ * 3];
__device__ __align__(16) __half g_pvec[NMAX * KTOT];
// g_Amat: batch-PAIR interleaved: [pair][element 0..59][2 batches]
__device__ __align__(16) float g_Amat[NMAX * NJ * 12];
__device__ __align__(16) __half g_B[C3PAD * KTOT];
__device__ __align__(16) float g_Wp[NW5];
__device__ __align__(16) float g_VTp[C3PAD];

// ---------------- helpers ----------------
__device__ __forceinline__ uint32_t smem_u32(const void* p) {
    uint32_t a;
    asm("{ .reg .u64 t; cvta.to.shared.u64 t, %1; cvt.u32.u64 %0, t; }" : "=r"(a) : "l"(p));
    return a;
}
__device__ __forceinline__ void mma_f16_16x8x16(float* d, const uint32_t* a,
                                                uint32_t b0, uint32_t b1) {
    asm volatile(
        "mma.sync.aligned.m16n8k16.row.col.f32.f16.f16.f32 "
        "{%0,%1,%2,%3}, {%4,%5,%6,%7}, {%8,%9}, {%0,%1,%2,%3};"
        : "+f"(d[0]), "+f"(d[1]), "+f"(d[2]), "+f"(d[3])
        : "r"(a[0]), "r"(a[1]), "r"(a[2]), "r"(a[3]), "r"(b0), "r"(b1));
}
#define LDSM_X4(r, addr)                                                     \
    asm volatile("ldmatrix.sync.aligned.m8n8.x4.shared.b16 {%0,%1,%2,%3}, [%4];" \
        : "=r"((r)[0]), "=r"((r)[1]), "=r"((r)[2]), "=r"((r)[3]) : "r"(addr))
__device__ __forceinline__ unsigned long long fma2(unsigned long long a,
                                                   unsigned long long b,
                                                   unsigned long long c) {
    unsigned long long d;
    asm("fma.rn.f32x2 %0, %1, %2, %3;" : "=l"(d) : "l"(a), "l"(b), "l"(c));
    return d;
}
__device__ __forceinline__ unsigned long long add2(unsigned long long a, unsigned long long b) {
    unsigned long long d;
    asm("add.rn.f32x2 %0, %1, %2;" : "=l"(d) : "l"(a), "l"(b));
    return d;
}
__device__ __forceinline__ unsigned long long packb(float x) {
    unsigned long long d;
    asm("mov.b64 %0, {%1, %1};" : "=l"(d) : "f"(x));
    return d;
}
__device__ __forceinline__ unsigned long long packp(float lo, float hi) {
    unsigned long long d;
    asm("mov.b64 %0, {%1, %2};" : "=l"(d) : "f"(lo), "f"(hi));
    return d;
}
__device__ __forceinline__ void unpk(unsigned long long v, float& lo, float& hi) {
    asm("mov.b64 {%0, %1}, %2;" : "=f"(lo), "=f"(hi) : "l"(v));
}
#define CP_ASYNC16(dst, src) \
    asm volatile("cp.async.cg.shared.global [%0], [%1], 16;" :: "r"(dst), "l"(src))
#define CP_COMMIT()  asm volatile("cp.async.commit_group;" ::: "memory")
#define CP_WAIT(n)   asm volatile("cp.async.wait_group %0;" :: "n"(n) : "memory")

// ---------------- kernel 0a ----------------
__global__ void k_zero() {
    int t = blockIdx.x * blockDim.x + threadIdx.x;
    if (t < NJ * 3 * 150) g_JS[t] = 0.0f;
    if (t < NJ * 3)       g_JT[t] = 0.0f;
}

// ---------------- kernel 0b: JS/JT reduction (157 blocks) + fused B build + pads ----------------
#define JSB 157
__global__ void k_prep(const float* __restrict__ Jr, const float* __restrict__ SD,
                       const float* __restrict__ PD, const float* __restrict__ VT,
                       const float* __restrict__ W) {
    if (blockIdx.x < JSB) {
        __shared__ float sJr[NJ][32];
        int vb = blockIdx.x * 32;
        int ve = vb + 32; if (ve > NV) ve = NV;
        int nv = ve - vb;
        int t = threadIdx.x;
        if (t < NJ * 32) {
            int j = t >> 5, v = t & 31;
            sJr[j][v] = (vb + v < NV) ? Jr[j * NV + vb + v] : 0.0f;
        }
        __syncthreads();
        if (t < 450) {
            float acc[NJ] = {0.f, 0.f, 0.f, 0.f, 0.f};
            for (int v = 0; v < nv; ++v) {
                float sd = SD[(vb + v) * 450 + t];
#pragma unroll
                for (int j = 0; j < NJ; j++) acc[j] = fmaf(sJr[j][v], sd, acc[j]);
            }
#pragma unroll
            for (int j = 0; j < NJ; j++) atomicAdd(&g_JS[j * 450 + t], acc[j]);
        } else if (t < 453) {
            int kc = t - 450;
            float acc[NJ] = {0.f, 0.f, 0.f, 0.f, 0.f};
            for (int v = 0; v < nv; ++v) {
                float vt = VT[(vb + v) * 3 + kc];
#pragma unroll
                for (int j = 0; j < NJ; j++) acc[j] = fmaf(sJr[j][v], vt, acc[j]);
            }
#pragma unroll
            for (int j = 0; j < NJ; j++) atomicAdd(&g_JT[j * 3 + kc], acc[j]);
        }
    } else {
        int idx = (blockIdx.x - JSB) * 512 + threadIdx.x;
        if (idx < NW5)   g_Wp[idx]  = (idx < NV * 5) ? W[idx]  : 0.0f;
        if (idx < C3PAD) g_VTp[idx] = (idx < C3)     ? VT[idx] : 0.0f;
        if (idx >= C3PAD * KTOT) return;
        int col = idx / KTOT;
        int k = idx - col * KTOT;
        float val = 0.0f;
        if (col < C3) {
            int v = col / 3, kc = col - v * 3;
            if (k < 150)      val = SD[v * 450 + kc * 150 + k];
            else if (k < 186) val = PD[(k - 150) * C3 + col];
        }
        g_B[idx] = __float2half_rn(val);
    }
}

// ---------------- rodrigues / chain ----------------
__device__ __forceinline__ void rodr(float x, float y, float z, float* R) {
    float a0 = x + 1e-8f, a1 = y + 1e-8f, a2 = z + 1e-8f;
    float ang = sqrtf(a0 * a0 + a1 * a1 + a2 * a2);
    float inv = 1.0f / ang;
    float rx = x * inv, ry = y * inv, rz = z * inv;
    float s = sinf(ang), c = cosf(ang), t = 1.0f - c;
    R[0] = 1.0f - t * (ry * ry + rz * rz);
    R[1] = t * rx * ry - s * rz;
    R[2] = t * rx * rz + s * ry;
    R[3] = t * rx * ry + s * rz;
    R[4] = 1.0f - t * (rx * rx + rz * rz);
    R[5] = t * ry * rz - s * rx;
    R[6] = t * rx * rz - s * ry;
    R[7] = t * ry * rz + s * rx;
    R[8] = 1.0f - t * (rx * rx + ry * ry);
}
__device__ __forceinline__ void mm3(const float* A, const float* B, float* C) {
#pragma unroll
    for (int r = 0; r < 3; r++)
#pragma unroll
        for (int c = 0; c < 3; c++)
            C[r * 3 + c] = A[r * 3 + 0] * B[0 + c] + A[r * 3 + 1] * B[3 + c] + A[r * 3 + 2] * B[6 + c];
}

// ---------------- kernel 1: per-batch params ----------------
__global__ __launch_bounds__(256) void k_batch(const float* __restrict__ shp, const float* __restrict__ ex,
                        const float* __restrict__ neck, const float* __restrict__ jaw,
                        const float* __restrict__ eye, int N) {
    __shared__ float sJS[2250];
    __shared__ float sJT[15];
    int tid = threadIdx.x;
    for (int i = tid; i < 2250; i += 256) sJS[i] = g_JS[i];
    if (tid < 15) sJT[tid] = g_JT[tid];
    __syncthreads();

    int b = (blockIdx.x * blockDim.x + tid) >> 5;
    int lane = tid & 31;
    if (b >= N) return;

    float Jp[15];
#pragma unroll
    for (int i = 0; i < 15; i++) Jp[i] = 0.0f;

    for (int l = lane; l < 150; l += 32) {
        float beta = (l < 100) ? shp[b * 100 + l] : ex[b * 50 + (l - 100)];
        g_pvec[b * KTOT + l] = __float2half_rn(beta);
#pragma unroll
        for (int jk = 0; jk < 15; jk++)
            Jp[jk] = fmaf(sJS[jk * 150 + l], beta, Jp[jk]);
    }
    for (int i = 150 + lane; i < KTOT; i += 32) g_pvec[b * KTOT + i] = __float2half_rn(0.0f);

#pragma unroll
    for (int jk = 0; jk < 15; jk++) {
#pragma unroll
        for (int off = 16; off; off >>= 1)
            Jp[jk] += __shfl_down_sync(0xffffffffu, Jp[jk], off);
    }
    __syncwarp();

    if (lane == 0) {
        float J[5][3];
#pragma unroll
        for (int j = 0; j < 5; j++)
#pragma unroll
            for (int kc = 0; kc < 3; kc++)
                J[j][kc] = Jp[j * 3 + kc] + sJT[j * 3 + kc];

        float R[5][9];
#pragma unroll
        for (int e = 0; e < 9; e++) R[0][e] = (e == 0 || e == 4 || e == 8) ? 1.0f : 0.0f;
        rodr(neck[b * 3 + 0], neck[b * 3 + 1], neck[b * 3 + 2], R[1]);
        rodr(jaw[b * 3 + 0],  jaw[b * 3 + 1],  jaw[b * 3 + 2],  R[2]);
        rodr(eye[b * 6 + 0],  eye[b * 6 + 1],  eye[b * 6 + 2],  R[3]);
        rodr(eye[b * 6 + 3],  eye[b * 6 + 4],  eye[b * 6 + 5],  R[4]);

        __half* pf = &g_pvec[b * KTOT + 150];
#pragma unroll
        for (int j = 1; j < 5; j++)
#pragma unroll
            for (int e = 0; e < 9; e++)
                pf[(j - 1) * 9 + e] = __float2half_rn(R[j][e] - ((e == 0 || e == 4 || e == 8) ? 1.0f : 0.0f));

        float Rg[5][9], tg[5][3];
#pragma unroll
        for (int e = 0; e < 9; e++) Rg[0][e] = R[0][e];
#pragma unroll
        for (int kc = 0; kc < 3; kc++) tg[0][kc] = J[0][kc];
#pragma unroll
        for (int i = 1; i < 5; i++) {
            const int p = (i == 1) ? 0 : 1;
            mm3(Rg[p], R[i], Rg[i]);
            float r0 = J[i][0] - J[p][0], r1 = J[i][1] - J[p][1], r2 = J[i][2] - J[p][2];
#pragma unroll
            for (int r = 0; r < 3; r++)
                tg[i][r] = Rg[p][r * 3 + 0] * r0 + Rg[p][r * 3 + 1] * r1 + Rg[p][r * 3 + 2] * r2 + tg[p][r];
        }
        float* Am = &g_Amat[(b >> 1) * 120 + (b & 1)];
#pragma unroll
        for (int j = 0; j < 5; j++)
#pragma unroll
            for (int r = 0; r < 3; r++) {
                Am[(j * 12 + r * 4 + 0) * 2] = Rg[j][r * 3 + 0];
                Am[(j * 12 + r * 4 + 1) * 2] = Rg[j][r * 3 + 1];
                Am[(j * 12 + r * 4 + 2) * 2] = Rg[j][r * 3 + 2];
                Am[(j * 12 + r * 4 + 3) * 2] = tg[j][r]
                    - (Rg[j][r * 3 + 0] * J[j][0] + Rg[j][r * 3 + 1] * J[j][1] + Rg[j][r * 3 + 2] * J[j][2]);
            }
    }
}

// ---------------- kernel 2: fp16 mma GEMM (ldmatrix frags, KC=64 x 3) + FFMA2 LBS ----------------
// GEMM bytes: bufA0@0 (18432) | bufB0@18432 (13824) | bufA1@32256 | bufB1@50688 | end 64512
// Epi region: sAm@64512 (30720, pair-interleaved) | sW@95232 (640) | sVt@95872 (384)
// res (f32 128x100) reuses [0, 51200) after GEMM.
#define STRH 72       // halfs per smem row (144 B)
#define OFF_A0 0
#define OFF_B0 18432
#define OFF_A1 32256
#define OFF_B1 50688
#define OFF_EAM 64512
#define OFF_EW  95232
#define OFF_EVT 95872
#define DYN_BYTES 96256

__global__ __launch_bounds__(256) void k_main(float* __restrict__ out, int N) {
    extern __shared__ float SM[];
    const uint32_t sbase = smem_u32(SM);

    const int tid = threadIdx.x;
    const int wid = tid >> 5, lane = tid & 31;
    const int q = lane & 3, g = lane >> 2;
    const int wm = wid & 3, wn = wid >> 2;
    const int v0 = blockIdx.x * 32;
    const int b0 = blockIdx.y * 128;

    const uint32_t offA[2] = {OFF_A0, OFF_A1};
    const uint32_t offB[2] = {OFF_B0, OFF_B1};

    auto load_chunk = [&](int ch, int bf) {
#pragma unroll
        for (int i = 0; i < 4; i++) {
            int idx = i * 256 + tid;
            int r = idx >> 3, s = idx & 7;
            int b = b0 + r; if (b >= N) b = N - 1;
            const __half* src = &g_pvec[b * KTOT + ch * KC + s * 8];
            CP_ASYNC16(sbase + offA[bf] + (r * STRH + s * 8) * 2, src);
        }
#pragma unroll
        for (int i = 0; i < 3; i++) {
            int idx = i * 256 + tid;
            int r = idx >> 3, s = idx & 7;
            const __half* src = &g_B[(v0 * 3 + r) * KTOT + ch * KC + s * 8];
            CP_ASYNC16(sbase + offB[bf] + (r * STRH + s * 8) * 2, src);
        }
    };

    // epilogue operand prefetch (padded/aligned sources), joins chunk-0 group
    {
#pragma unroll
        for (int i = 0; i < 8; i++) {
            int seg = i * 256 + tid;
            if (seg < 1920) {
                int gi = b0 * 60 + seg * 4;
                if (gi + 4 > N * 60) gi = N * 60 - 4;
                CP_ASYNC16(sbase + OFF_EAM + seg * 16, &g_Amat[gi]);
            }
        }
        if (tid < 40) CP_ASYNC16(sbase + OFF_EW + tid * 16, &g_Wp[v0 * 5 + tid * 4]);
        if (tid < 24) CP_ASYNC16(sbase + OFF_EVT + tid * 16, &g_VTp[v0 * 3 + tid * 4]);
    }
    load_chunk(0, 0);
    CP_COMMIT();

    // ldmatrix lane base addresses (bytes from smem base, buffer offset added per use)
    const uint32_t rowA = wm * 32 + ((lane >> 3) & 1) * 8 + (lane & 7);
    const uint32_t koffA = (lane >> 4) * 8;
    const uint32_t aBase = sbase + rowA * (STRH * 2) + koffA * 2;
    const uint32_t rowB = wn * 48 + ((lane >> 4) & 1) * 8 + (lane & 7);
    const uint32_t koffB = ((lane >> 3) & 1) * 8;
    const uint32_t bBase = sbase + rowB * (STRH * 2) + koffB * 2;

    float acc[2][6][4];
#pragma unroll
    for (int mi = 0; mi < 2; mi++)
#pragma unroll
        for (int ni = 0; ni < 6; ni++)
#pragma unroll
            for (int r = 0; r < 4; r++) acc[mi][ni][r] = 0.0f;

    for (int ch = 0; ch < NCH; ++ch) {
        const int bf = ch & 1;
        if (ch + 1 < NCH) {
            load_chunk(ch + 1, (ch + 1) & 1);
            CP_COMMIT();
            CP_WAIT(1);
        } else {
            CP_WAIT(0);
        }
        __syncthreads();

        const uint32_t aB = aBase + offA[bf];
        const uint32_t bB = bBase + offB[bf];

#pragma unroll
        for (int s = 0; s < 4; s++) {
            uint32_t a[2][4], bfr[3][4];
            LDSM_X4(a[0], aB + s * 32);
            LDSM_X4(a[1], aB + 2304 + s * 32);     // +16 rows * 144 B
#pragma unroll
            for (int t = 0; t < 3; t++)
                LDSM_X4(bfr[t], bB + t * 2304 + s * 32);
#pragma unroll
            for (int mi = 0; mi < 2; mi++)
#pragma unroll
                for (int ni = 0; ni < 6; ni++)
                    mma_f16_16x8x16(acc[mi][ni], a[mi],
                                    bfr[ni >> 1][(ni & 1) * 2],
                                    bfr[ni >> 1][(ni & 1) * 2 + 1]);
        }
        __syncthreads();
    }

    // ---------------- stage GEMM result ----------------
    float* res = SM;                         // 128x100 f32
    const float* sAm = (const float*)((char*)SM + OFF_EAM);  // pair-interleaved
    const float* sW  = (const float*)((char*)SM + OFF_EW);
    const float* sVt = (const float*)((char*)SM + OFF_EVT);
#pragma unroll
    for (int mi = 0; mi < 2; mi++)
#pragma unroll
        for (int ni = 0; ni < 6; ni++)
#pragma unroll
            for (int r = 0; r < 4; r++) {
                int row = wm * 32 + mi * 16 + g + (r >> 1) * 8;
                int col = wn * 48 + ni * 8 + q * 2 + (r & 1);
                res[row * 100 + col] = acc[mi][ni][r];
            }
    __syncthreads();

    // ---------------- FFMA2 LBS, packed across batch pairs ----------------
    const int vg = tid & 7;     // 4 vertices per thread
    const int bg = tid >> 3;    // 4 batches = 2 pairs per thread

    unsigned long long wb[4][5], vtb[4][3];
#pragma unroll
    for (int vi = 0; vi < 4; vi++) {
        int vl = vg * 4 + vi;
#pragma unroll
        for (int j = 0; j < 5; j++) wb[vi][j] = packb(sW[vl * 5 + j]);
#pragma unroll
        for (int m = 0; m < 3; m++) vtb[vi][m] = packb(sVt[vl * 3 + m]);
    }

#pragma unroll
    for (int u = 0; u < 2; u++) {
        const int pl = bg * 2 + u;
        const unsigned long long* Ap =
            (const unsigned long long*)&sAm[pl * 120];
        float* r0p = &res[(2 * pl) * 100];
        float* r1p = &res[(2 * pl + 1) * 100];

        unsigned long long vp2[4][3];
#pragma unroll
        for (int vi = 0; vi < 4; vi++) {
            int c = (vg * 4 + vi) * 3;
#pragma unroll
            for (int m = 0; m < 3; m++)
                vp2[vi][m] = add2(packp(r0p[c + m], r1p[c + m]), vtb[vi][m]);
        }

#pragma unroll
        for (int r = 0; r < 3; r++) {
            unsigned long long A2[5][4];
#pragma unroll
            for (int j = 0; j < 5; j++)
#pragma unroll
                for (int m = 0; m < 4; m++)
                    A2[j][m] = Ap[j * 12 + r * 4 + m];
#pragma unroll
            for (int vi = 0; vi < 4; vi++) {
                unsigned long long s2 = 0ULL;
#pragma unroll
                for (int j = 0; j < 5; j++) {
                    unsigned long long t2 =
                        fma2(A2[j][0], vp2[vi][0],
                        fma2(A2[j][1], vp2[vi][1],
                        fma2(A2[j][2], vp2[vi][2], A2[j][3])));
                    s2 = fma2(wb[vi][j], t2, s2);
                }
                float lo, hi;
                unpk(s2, lo, hi);
                int c = (vg * 4 + vi) * 3 + r;
                r0p[c] = lo;
                r1p[c] = hi;
            }
        }
    }
    __syncthreads();

    // ---------------- coalesced store ----------------
    const int cmax = C3 - v0 * 3;
#pragma unroll
    for (int i = 0; i < 48; i++) {
        int idx = i * 256 + tid;
        int bl = idx / 96, c = idx - bl * 96;
        int b = b0 + bl;
        if (b < N && c < cmax)
            out[(size_t)b * C3 + v0 * 3 + c] = res[bl * 100 + c];
    }
}

// ---------------- launch ----------------
extern "C" void kernel_launch(void* const* d_in, const int* in_sizes, int n_in,
                              void* d_out, int out_size) {
    const float* shp  = (const float*)d_in[0];
    const float* ex   = (const float*)d_in[1];
    const float* neck = (const float*)d_in[2];
    const float* jaw  = (const float*)d_in[3];
    const float* eye  = (const float*)d_in[4];
    const float* vt   = (const float*)d_in[5];
    const float* sd   = (const float*)d_in[6];
    const float* pd   = (const float*)d_in[7];
    const float* jr   = (const float*)d_in[8];
    const float* lw   = (const float*)d_in[9];
    int N = in_sizes[0] / 100;
    if (N > NMAX) N = NMAX;

    static int smem_set = 0;
    if (!smem_set) {
        cudaFuncSetAttribute(k_main, cudaFuncAttributeMaxDynamicSharedMemorySize, DYN_BYTES);
        smem_set = 1;
    }

    k_zero<<<9, 256>>>();
    k_prep<<<JSB + (C3PAD * KTOT + 511) / 512, 512>>>(jr, sd, pd, vt, lw);
    k_batch<<<(N + 7) / 8, 256>>>(shp, ex, neck, jaw, eye, N);

    dim3 grid((NV + 31) / 32, (N + 127) / 128);
    k_main<<<grid, 256, DYN_BYTES>>>((float*)d_out, N);
}